// round 6
// baseline (speedup 1.0000x reference)
#include <cuda_runtime.h>
#include <cuda_bf16.h>
#include <cstdint>

// Problem constants (fixed shapes)
constexpr int T_ = 2048;
constexpr int S_ = 2048;
constexpr int B_ = 2;
constexpr int E_ = 1024;
constexpr int H_ = 16;
constexpr int D_ = 64;
constexpr int M_ = T_ * B_;   // 4096

// ---------------------------------------------------------------------------
// Scratch (__device__ globals; allocations forbidden)
// ---------------------------------------------------------------------------
__device__ __nv_bfloat16 g_iqh[M_ * E_], g_iql[M_ * E_];
__device__ __nv_bfloat16 g_ikh[M_ * E_], g_ikl[M_ * E_];
__device__ __nv_bfloat16 g_ivh[M_ * E_], g_ivl[M_ * E_];
__device__ __nv_bfloat16 g_wh[4][E_ * E_], g_wl[4][E_ * E_];
__device__ __nv_bfloat16 g_pqh[B_ * H_ * T_ * D_], g_pql[B_ * H_ * T_ * D_];
__device__ __nv_bfloat16 g_pkh[B_ * H_ * S_ * D_], g_pkl[B_ * H_ * S_ * D_];
__device__ __nv_bfloat16 g_pvh[B_ * H_ * S_ * D_], g_pvl[B_ * H_ * S_ * D_];
__device__ __nv_bfloat16 g_ch[M_ * E_], g_cl[M_ * E_];
__device__ float g_kpf[B_ * S_];

// ---------------------------------------------------------------------------
// PTX helpers (generic PTX only)
// ---------------------------------------------------------------------------
__device__ __forceinline__ uint32_t smem_u32(const void* p) {
    uint32_t a;
    asm("{ .reg .u64 t; cvta.to.shared.u64 t, %1; cvt.u32.u64 %0, t; }"
        : "=r"(a) : "l"(p));
    return a;
}
__device__ __forceinline__ void cp16(uint32_t dst, const void* src) {
    asm volatile("cp.async.cg.shared.global [%0], [%1], 16;" :: "r"(dst), "l"(src));
}
__device__ __forceinline__ void cp_commit() {
    asm volatile("cp.async.commit_group;" ::: "memory");
}
template <int N>
__device__ __forceinline__ void cp_wait() {
    asm volatile("cp.async.wait_group %0;" :: "n"(N) : "memory");
}
__device__ __forceinline__ void ldsm4(uint32_t& r0, uint32_t& r1, uint32_t& r2,
                                      uint32_t& r3, uint32_t addr) {
    asm volatile("ldmatrix.sync.aligned.m8n8.x4.shared.b16 {%0,%1,%2,%3}, [%4];"
                 : "=r"(r0), "=r"(r1), "=r"(r2), "=r"(r3) : "r"(addr));
}
__device__ __forceinline__ void ldsm4t(uint32_t* r, uint32_t addr) {
    asm volatile("ldmatrix.sync.aligned.m8n8.x4.trans.shared.b16 {%0,%1,%2,%3}, [%4];"
                 : "=r"(r[0]), "=r"(r[1]), "=r"(r[2]), "=r"(r[3]) : "r"(addr));
}
__device__ __forceinline__ void mma_bf16(float* c, const uint32_t* a,
                                         uint32_t b0, uint32_t b1) {
    asm volatile(
        "mma.sync.aligned.m16n8k16.row.col.f32.bf16.bf16.f32 "
        "{%0,%1,%2,%3}, {%4,%5,%6,%7}, {%8,%9}, {%0,%1,%2,%3};"
        : "+f"(c[0]), "+f"(c[1]), "+f"(c[2]), "+f"(c[3])
        : "r"(a[0]), "r"(a[1]), "r"(a[2]), "r"(a[3]), "r"(b0), "r"(b1));
}
__device__ __forceinline__ uint32_t packbf(float x, float y) {
    __nv_bfloat162 t = __floats2bfloat162_rn(x, y);
    return *reinterpret_cast<uint32_t*>(&t);
}
__device__ __forceinline__ float2 unpackbf(uint32_t u) {
    __nv_bfloat162 t = *reinterpret_cast<__nv_bfloat162*>(&u);
    return make_float2(__bfloat162float(t.x), __bfloat162float(t.y));
}

// ---------------------------------------------------------------------------
// Batched convert fp32 -> (bf16 hi, bf16 lo): 7 jobs in one launch
// ---------------------------------------------------------------------------
struct CvtJob { const float4* src; uint2* hi; uint2* lo; int n4; };
struct CvtJobs { CvtJob j[7]; };

__global__ void __launch_bounds__(256)
convert_all(CvtJobs jobs)
{
    const CvtJob jb = jobs.j[blockIdx.y];
    const int i = blockIdx.x * 256 + threadIdx.x;
    if (i >= jb.n4) return;
    float4 v = jb.src[i];
    __nv_bfloat16 h[4], l[4];
    float f[4] = {v.x, v.y, v.z, v.w};
    #pragma unroll
    for (int j = 0; j < 4; j++) {
        h[j] = __float2bfloat16(f[j]);
        l[j] = __float2bfloat16(f[j] - __bfloat162float(h[j]));
    }
    jb.hi[i] = *reinterpret_cast<uint2*>(h);
    jb.lo[i] = *reinterpret_cast<uint2*>(l);
}

__global__ void kpad_to_float(const unsigned char* __restrict__ kp,
                              float* __restrict__ out, int n)
{
    int i = blockIdx.x * 256 + threadIdx.x;
    if (i < n) out[i] = kp[i] ? -1e9f : 0.f;
}

// ---------------------------------------------------------------------------
// HMMA GEMM: tile 128x128, BK=32, 8 warps (warp 64x32), 3-term bf16 split.
// __launch_bounds__(256,2): cap regs at 128 so 2 CTAs/SM co-reside (smem 64KB).
// OUT_MODE 0: bf16 hi/lo head-major [B,H,T,D]. OUT_MODE 1: fp32 [M,E].
// ---------------------------------------------------------------------------
struct GemmJob {
    const __nv_bfloat16 *Ah, *Al, *Wh, *Wl;
    const float* bias;
    __nv_bfloat16 *Chi, *Clo;
    float* Cf;
    float scale;
};
struct GemmJobs3 { GemmJob j[3]; };

constexpr int G_STAGE = 32768;
constexpr int G_SMEM  = 2 * G_STAGE;   // 64 KB

__device__ __forceinline__ uint32_t sw_addr(int row, int byte_in_row) {
    uint32_t b = (uint32_t)(row * 64 + byte_in_row);
    return b ^ (((uint32_t)row & 3u) << 4);
}

__device__ __forceinline__ void g_load(
    uint32_t sdst, const GemmJob& jb, int bm, int bn, int k0, int tid)
{
    const __nv_bfloat16* srcs[4] = {jb.Ah, jb.Al, jb.Wh, jb.Wl};
    const int rbase[4] = {bm, bm, bn, bn};
    #pragma unroll
    for (int i = 0; i < 8; i++) {
        const int id = tid + i * 256;
        const int sub = id >> 9;
        const int lin = id & 511;
        const int row = lin >> 2, c = lin & 3;
        cp16(sdst + sub * 8192 + sw_addr(row, c * 16),
             srcs[sub] + (size_t)(rbase[sub] + row) * E_ + k0 + c * 8);
    }
}

template <int OUT_MODE>
__global__ void __launch_bounds__(256, 2)
gemm_tc(GemmJobs3 jobs)
{
    extern __shared__ char smem[];
    const uint32_t sbase = smem_u32(smem);
    const GemmJob jb = jobs.j[blockIdx.z];
    const int tid = threadIdx.x;
    const int warp = tid >> 5;
    const int lane = tid & 31;
    const int bm = blockIdx.x * 128;
    const int bn = blockIdx.y * 128;

    const int wm = (warp >> 2) * 64;
    const int wn = (warp & 3) * 32;

    float acc[4][4][4] = {};
    const int lrow = lane & 15;
    const int lseg = lane >> 4;

    g_load(sbase, jb, bm, bn, 0, tid);
    cp_commit();

    for (int chunk = 0; chunk < 32; chunk++) {
        const int s = chunk & 1;
        cp_wait<0>();
        __syncthreads();
        if (chunk < 31) {
            g_load(sbase + (s ^ 1) * G_STAGE, jb, bm, bn, (chunk + 1) * 32, tid);
            cp_commit();
        }
        const uint32_t st = sbase + s * G_STAGE;
        #pragma unroll
        for (int kk = 0; kk < 2; kk++) {
            const int c16 = (kk * 2 + lseg) * 16;
            uint32_t ah[4][4], al[4][4], bh[2][4], bl[2][4];
            #pragma unroll
            for (int mi = 0; mi < 4; mi++) {
                const uint32_t a = sw_addr(wm + mi * 16 + lrow, c16);
                ldsm4(ah[mi][0], ah[mi][1], ah[mi][2], ah[mi][3], st + a);
                ldsm4(al[mi][0], al[mi][1], al[mi][2], al[mi][3], st + 8192 + a);
            }
            #pragma unroll
            for (int nb = 0; nb < 2; nb++) {
                const uint32_t a = sw_addr(wn + nb * 16 + lrow, c16);
                ldsm4(bh[nb][0], bh[nb][1], bh[nb][2], bh[nb][3], st + 16384 + a);
                ldsm4(bl[nb][0], bl[nb][1], bl[nb][2], bl[nb][3], st + 24576 + a);
            }
            #pragma unroll
            for (int mi = 0; mi < 4; mi++) {
                #pragma unroll
                for (int ni = 0; ni < 4; ni++) {
                    const int nb = ni >> 1, hp = ni & 1;
                    mma_bf16(acc[mi][ni], ah[mi], bh[nb][hp], bh[nb][hp + 2]);
                    mma_bf16(acc[mi][ni], ah[mi], bl[nb][hp], bl[nb][hp + 2]);
                    mma_bf16(acc[mi][ni], al[mi], bh[nb][hp], bh[nb][hp + 2]);
                }
            }
        }
    }

    #pragma unroll
    for (int mi = 0; mi < 4; mi++) {
        #pragma unroll
        for (int ni = 0; ni < 4; ni++) {
            const int col = bn + wn + ni * 8 + (lane & 3) * 2;
            const float b0 = jb.bias[col], b1 = jb.bias[col + 1];
            #pragma unroll
            for (int half = 0; half < 2; half++) {
                const int m = bm + wm + mi * 16 + (lane >> 2) + half * 8;
                float ox = (acc[mi][ni][half * 2 + 0] + b0) * jb.scale;
                float oy = (acc[mi][ni][half * 2 + 1] + b1) * jb.scale;
                if (OUT_MODE == 0) {
                    const int t = m >> 1, b = m & 1;   // m = t*B + b, B=2
                    const int h = col >> 6, dd = col & 63;
                    const size_t idx = ((size_t)(b * H_ + h) * T_ + t) * D_ + dd;
                    uint32_t hp_ = packbf(ox, oy);
                    float2 hf = unpackbf(hp_);
                    uint32_t lp_ = packbf(ox - hf.x, oy - hf.y);
                    *(uint32_t*)&jb.Chi[idx] = hp_;
                    *(uint32_t*)&jb.Clo[idx] = lp_;
                } else {
                    *(float2*)&jb.Cf[(size_t)m * E_ + col] = make_float2(ox, oy);
                }
            }
        }
    }
}

// ---------------------------------------------------------------------------
// Flash attention via HMMA with a 1-tile software pipeline:
// each iteration issues scores(tile+1) MMAs first, then softmax+PV(tile),
// so MUFU/shuffle latency overlaps outstanding tensor work in the same warp.
// CTA: 128 q-rows of one (b,h); 8 warps x 16 rows; 64-key tiles, 2 stages.
// ---------------------------------------------------------------------------
constexpr uint32_t FA_OFF_QL  = 16384;
constexpr uint32_t FA_OFF_ST  = 32768;
constexpr uint32_t FA_ST_B    = 32768;
constexpr uint32_t FA_OFF_M   = 98304;
constexpr uint32_t FA_M_B     = 36864;   // 128 rows x 288 bytes
constexpr uint32_t FA_OFF_KPF = FA_OFF_M + 2 * FA_M_B;    // 172032
constexpr int FA_SMEM = (int)FA_OFF_KPF + 512;

__device__ __forceinline__ uint32_t fa_off(int row, int chunk) {
    return (uint32_t)(row * 128 + ((chunk ^ (row & 7)) << 4));
}

__device__ __forceinline__ void fa_load_stage(
    uint32_t sbase, int stage,
    const __nv_bfloat16* __restrict__ kh, const __nv_bfloat16* __restrict__ kl,
    const __nv_bfloat16* __restrict__ vh, const __nv_bfloat16* __restrict__ vl,
    const float* __restrict__ maskg, const float* __restrict__ kpf,
    int t0, int s0, int tid)
{
    const __nv_bfloat16* srcs[4] = {kh, kl, vh, vl};
    #pragma unroll
    for (int i = 0; i < 8; i++) {
        const int id = tid + i * 256;
        const int sub = id >> 9;
        const int lin = id & 511;
        const int row = lin >> 3;
        const int c   = lin & 7;
        cp16(sbase + FA_OFF_ST + stage * FA_ST_B + sub * 8192 + fa_off(row, c),
             srcs[sub] + (size_t)(s0 + row) * D_ + c * 8);
    }
    #pragma unroll
    for (int i = 0; i < 8; i++) {
        const int id = tid + i * 256;
        const int row = id >> 4;
        const int c16 = id & 15;
        cp16(sbase + FA_OFF_M + stage * FA_M_B + row * 288 + c16 * 16,
             maskg + (size_t)(t0 + row) * S_ + s0 + c16 * 4);
    }
    if (tid < 16)
        cp16(sbase + FA_OFF_KPF + stage * 256 + tid * 16, kpf + s0 + tid * 4);
}

__global__ void __launch_bounds__(256)
flash_mma(const __nv_bfloat16* __restrict__ qh_g, const __nv_bfloat16* __restrict__ ql_g,
          const __nv_bfloat16* __restrict__ kh_g, const __nv_bfloat16* __restrict__ kl_g,
          const __nv_bfloat16* __restrict__ vh_g, const __nv_bfloat16* __restrict__ vl_g,
          const float* __restrict__ maskg, const float* __restrict__ kpf_g,
          __nv_bfloat16* __restrict__ ch, __nv_bfloat16* __restrict__ cl)
{
    extern __shared__ char smem[];
    const uint32_t sbase = smem_u32(smem);
    const int tid = threadIdx.x;
    const int lane = tid & 31;
    const int warp = tid >> 5;
    const int t0 = blockIdx.x * 128;
    const int h = blockIdx.y;
    const int b = blockIdx.z;

    const size_t hoff = (size_t)(b * H_ + h);
    const __nv_bfloat16* qh = qh_g + (hoff * T_ + t0) * D_;
    const __nv_bfloat16* ql = ql_g + (hoff * T_ + t0) * D_;
    const __nv_bfloat16* kh = kh_g + hoff * S_ * D_;
    const __nv_bfloat16* kl = kl_g + hoff * S_ * D_;
    const __nv_bfloat16* vh = vh_g + hoff * S_ * D_;
    const __nv_bfloat16* vl = vl_g + hoff * S_ * D_;
    const float* kpf = kpf_g + b * S_;

    // Q tile load (128x64 hi/lo) — grouped with stage 0
    #pragma unroll
    for (int i = 0; i < 8; i++) {
        const int id = tid + i * 256;
        const int sub = id >> 10;
        const int lin = id & 1023;
        const int row = lin >> 3;
        const int c   = lin & 7;
        cp16(sbase + sub * FA_OFF_QL + fa_off(row, c),
             (sub ? ql : qh) + (size_t)row * D_ + c * 8);
    }
    fa_load_stage(sbase, 0, kh, kl, vh, vl, maskg, kpf, t0, 0, tid);
    cp_commit();
    fa_load_stage(sbase, 1, kh, kl, vh, vl, maskg, kpf, t0, 64, tid);
    cp_commit();

    const int wm = warp * 16;
    const int lrow = lane & 15;
    const int lseg = lane >> 4;
    const int qr = lane >> 2;
    const int qc = (lane & 3) * 2;
    const uint32_t ones = ((lane >> 2) == 0) ? 0x3F803F80u : 0u;

    float acc[8][4] = {};
    float lf[4] = {};
    float m0 = -1e30f, m1 = -1e30f;
    float sc_cur[8][4], sc_next[8][4];

    // scores helper as a macro-ish lambda (keeps register naming tight)
    auto scores_into = [&](float (&sc)[8][4], uint32_t stk) {
        #pragma unroll
        for (int j = 0; j < 8; j++) {
            sc[j][0] = 0.f; sc[j][1] = 0.f; sc[j][2] = 0.f; sc[j][3] = 0.f;
        }
        #pragma unroll
        for (int kk = 0; kk < 4; kk++) {
            uint32_t ah[4], al[4];
            ldsm4(ah[0], ah[1], ah[2], ah[3],
                  sbase + fa_off(wm + lrow, kk * 2 + lseg));
            ldsm4(al[0], al[1], al[2], al[3],
                  sbase + FA_OFF_QL + fa_off(wm + lrow, kk * 2 + lseg));
            #pragma unroll
            for (int nb = 0; nb < 4; nb++) {
                uint32_t bh[4], bl[4];
                ldsm4(bh[0], bh[1], bh[2], bh[3],
                      stk + fa_off(nb * 16 + lrow, kk * 2 + lseg));
                ldsm4(bl[0], bl[1], bl[2], bl[3],
                      stk + 8192 + fa_off(nb * 16 + lrow, kk * 2 + lseg));
                #pragma unroll
                for (int hp = 0; hp < 2; hp++) {
                    float* sf = sc[nb * 2 + hp];
                    mma_bf16(sf, ah, bh[hp], bh[hp + 2]);
                    mma_bf16(sf, ah, bl[hp], bl[hp + 2]);
                    mma_bf16(sf, al, bh[hp], bh[hp + 2]);
                }
            }
        }
    };

    // prologue: stage0 ready, compute scores(0)
    cp_wait<1>();
    __syncthreads();
    scores_into(sc_cur, sbase + FA_OFF_ST);

    for (int tile = 0; tile < 32; tile++) {
        const int stg = tile & 1;

        // (a,b) issue scores(tile+1) on the other stage — tensor gets busy
        if (tile < 31) {
            cp_wait<0>();
            __syncthreads();
            scores_into(sc_next, sbase + FA_OFF_ST + (stg ^ 1) * FA_ST_B);
        }

        // (c) softmax(tile) on sc_cur (+ masks from stage stg)
        {
            const float* kpfs = (const float*)(smem + FA_OFF_KPF + stg * 256);
            const float* ms   = (const float*)(smem + FA_OFF_M + stg * FA_M_B);
            const int r0s = (wm + qr) * 72, r1s = r0s + 8 * 72;
            #pragma unroll
            for (int j = 0; j < 8; j++) {
                float2 k2 = *(const float2*)&kpfs[j * 8 + qc];
                float2 a0 = *(const float2*)&ms[r0s + j * 8 + qc];
                float2 a1 = *(const float2*)&ms[r1s + j * 8 + qc];
                sc_cur[j][0] += a0.x + k2.x; sc_cur[j][1] += a0.y + k2.y;
                sc_cur[j][2] += a1.x + k2.x; sc_cur[j][3] += a1.y + k2.y;
            }

            float tm0 = -1e30f, tm1 = -1e30f;
            #pragma unroll
            for (int j = 0; j < 8; j++) {
                tm0 = fmaxf(tm0, fmaxf(sc_cur[j][0], sc_cur[j][1]));
                tm1 = fmaxf(tm1, fmaxf(sc_cur[j][2], sc_cur[j][3]));
            }
            tm0 = fmaxf(tm0, __shfl_xor_sync(0xffffffffu, tm0, 1, 4));
            tm0 = fmaxf(tm0, __shfl_xor_sync(0xffffffffu, tm0, 2, 4));
            tm1 = fmaxf(tm1, __shfl_xor_sync(0xffffffffu, tm1, 1, 4));
            tm1 = fmaxf(tm1, __shfl_xor_sync(0xffffffffu, tm1, 2, 4));
            const float mn0 = fmaxf(m0, tm0), mn1 = fmaxf(m1, tm1);
            const float cr0 = __expf(m0 - mn0), cr1 = __expf(m1 - mn1);
            m0 = mn0; m1 = mn1;
            #pragma unroll
            for (int j = 0; j < 8; j++) {
                sc_cur[j][0] = __expf(sc_cur[j][0] - mn0);
                sc_cur[j][1] = __expf(sc_cur[j][1] - mn0);
                sc_cur[j][2] = __expf(sc_cur[j][2] - mn1);
                sc_cur[j][3] = __expf(sc_cur[j][3] - mn1);
            }
            #pragma unroll
            for (int j = 0; j < 8; j++) {
                acc[j][0] *= cr0; acc[j][1] *= cr0;
                acc[j][2] *= cr1; acc[j][3] *= cr1;
            }
            lf[0] *= cr0; lf[1] *= cr0; lf[2] *= cr1; lf[3] *= cr1;
        }

        // (d) PV(tile): O += Ph Vh + Ph Vl + Pl Vh ; l += (Ph+Pl) @ ones
        {
            const uint32_t stk = sbase + FA_OFF_ST + stg * FA_ST_B;
            #pragma unroll
            for (int kk = 0; kk < 4; kk++) {
                const int j0 = 2 * kk, j1 = j0 + 1;
                uint32_t ph[4], pl[4];
                {
                    float px[8] = {sc_cur[j0][0], sc_cur[j0][1], sc_cur[j0][2], sc_cur[j0][3],
                                   sc_cur[j1][0], sc_cur[j1][1], sc_cur[j1][2], sc_cur[j1][3]};
                    #pragma unroll
                    for (int q = 0; q < 4; q++) {
                        uint32_t hp_ = packbf(px[2 * q], px[2 * q + 1]);
                        float2 hf = unpackbf(hp_);
                        ph[q] = hp_;
                        pl[q] = packbf(px[2 * q] - hf.x, px[2 * q + 1] - hf.y);
                    }
                }
                #pragma unroll
                for (int ng = 0; ng < 4; ng++) {
                    uint32_t v4[4], w4[4];
                    ldsm4t(v4, stk + 16384 + fa_off(kk * 16 + lrow, ng * 2 + lseg));
                    ldsm4t(w4, stk + 24576 + fa_off(kk * 16 + lrow, ng * 2 + lseg));
                    mma_bf16(acc[ng * 2 + 0], ph, v4[0], v4[1]);
                    mma_bf16(acc[ng * 2 + 0], ph, w4[0], w4[1]);
                    mma_bf16(acc[ng * 2 + 0], pl, v4[0], v4[1]);
                    mma_bf16(acc[ng * 2 + 1], ph, v4[2], v4[3]);
                    mma_bf16(acc[ng * 2 + 1], ph, w4[2], w4[3]);
                    mma_bf16(acc[ng * 2 + 1], pl, v4[2], v4[3]);
                }
                mma_bf16(lf, ph, ones, ones);
                mma_bf16(lf, pl, ones, ones);
            }
        }

        // (e,f) stage stg fully consumed — prefetch tile+2 into it
        __syncthreads();
        if (tile < 30) {
            fa_load_stage(sbase, stg, kh, kl, vh, vl, maskg, kpf,
                          t0, (tile + 2) * 64, tid);
            cp_commit();
        }

        // (g) rotate score buffers
        if (tile < 31) {
            #pragma unroll
            for (int j = 0; j < 8; j++) {
                sc_cur[j][0] = sc_next[j][0]; sc_cur[j][1] = sc_next[j][1];
                sc_cur[j][2] = sc_next[j][2]; sc_cur[j][3] = sc_next[j][3];
            }
        }
    }

    // ---- epilogue: normalize, write ctx bf16 hi/lo [t*B+b][E] ----
    const float l0 = __shfl_sync(0xffffffffu, lf[0], 0, 4);
    const float l1 = __shfl_sync(0xffffffffu, lf[2], 0, 4);
    const float inv0 = 1.f / l0, inv1 = 1.f / l1;
    const int r0 = t0 + wm + qr, r1 = r0 + 8;
    #pragma unroll
    for (int j = 0; j < 8; j++) {
        const int col = h * D_ + j * 8 + qc;
        {
            float x = acc[j][0] * inv0, y = acc[j][1] * inv0;
            uint32_t hp_ = packbf(x, y);
            float2 hf = unpackbf(hp_);
            uint32_t lp_ = packbf(x - hf.x, y - hf.y);
            const size_t idx = ((size_t)r0 * B_ + b) * E_ + col;
            *(uint32_t*)&ch[idx] = hp_;
            *(uint32_t*)&cl[idx] = lp_;
        }
        {
            float x = acc[j][2] * inv1, y = acc[j][3] * inv1;
            uint32_t hp_ = packbf(x, y);
            float2 hf = unpackbf(hp_);
            uint32_t lp_ = packbf(x - hf.x, y - hf.y);
            const size_t idx = ((size_t)r1 * B_ + b) * E_ + col;
            *(uint32_t*)&ch[idx] = hp_;
            *(uint32_t*)&cl[idx] = lp_;
        }
    }
}

// ---------------------------------------------------------------------------
// Launch
// ---------------------------------------------------------------------------
extern "C" void kernel_launch(void* const* d_in, const int* in_sizes, int n_in,
                              void* d_out, int out_size)
{
    const float* query = (const float*)d_in[0];
    const float* key   = (const float*)d_in[1];
    const float* value = (const float*)d_in[2];
    const float* amask = (const float*)d_in[3];
    const unsigned char* kpad = (const unsigned char*)d_in[4];
    const float* Wq = (const float*)d_in[5];
    const float* bq = (const float*)d_in[6];
    const float* Wk = (const float*)d_in[7];
    const float* bk = (const float*)d_in[8];
    const float* Wv = (const float*)d_in[9];
    const float* bv = (const float*)d_in[10];
    const float* Wo = (const float*)d_in[11];
    const float* bo = (const float*)d_in[12];
    float* out = (float*)d_out;

    __nv_bfloat16 *iqh, *iql, *ikh, *ikl, *ivh, *ivl, *wh, *wl;
    __nv_bfloat16 *pqh, *pql, *pkh, *pkl, *pvh, *pvl, *ch, *cl;
    float* kpf;
    cudaGetSymbolAddress((void**)&iqh, g_iqh); cudaGetSymbolAddress((void**)&iql, g_iql);
    cudaGetSymbolAddress((void**)&ikh, g_ikh); cudaGetSymbolAddress((void**)&ikl, g_ikl);
    cudaGetSymbolAddress((void**)&ivh, g_ivh); cudaGetSymbolAddress((void**)&ivl, g_ivl);
    cudaGetSymbolAddress((void**)&wh, g_wh);   cudaGetSymbolAddress((void**)&wl, g_wl);
    cudaGetSymbolAddress((void**)&pqh, g_pqh); cudaGetSymbolAddress((void**)&pql, g_pql);
    cudaGetSymbolAddress((void**)&pkh, g_pkh); cudaGetSymbolAddress((void**)&pkl, g_pkl);
    cudaGetSymbolAddress((void**)&pvh, g_pvh); cudaGetSymbolAddress((void**)&pvl, g_pvl);
    cudaGetSymbolAddress((void**)&ch, g_ch);   cudaGetSymbolAddress((void**)&cl, g_cl);
    cudaGetSymbolAddress((void**)&kpf, g_kpf);

    cudaFuncSetAttribute(gemm_tc<0>, cudaFuncAttributeMaxDynamicSharedMemorySize, G_SMEM);
    cudaFuncSetAttribute(gemm_tc<1>, cudaFuncAttributeMaxDynamicSharedMemorySize, G_SMEM);
    cudaFuncSetAttribute(flash_mma, cudaFuncAttributeMaxDynamicSharedMemorySize, FA_SMEM);

    const int nIn4 = M_ * E_ / 4;
    const int nW4  = E_ * E_ / 4;

    CvtJobs cj;
    cj.j[0] = {(const float4*)query, (uint2*)iqh, (uint2*)iql, nIn4};
    cj.j[1] = {(const float4*)key,   (uint2*)ikh, (uint2*)ikl, nIn4};
    cj.j[2] = {(const float4*)value, (uint2*)ivh, (uint2*)ivl, nIn4};
    cj.j[3] = {(const float4*)Wq, (uint2*)(wh + 0 * E_ * E_), (uint2*)(wl + 0 * E_ * E_), nW4};
    cj.j[4] = {(const float4*)Wk, (uint2*)(wh + 1 * E_ * E_), (uint2*)(wl + 1 * E_ * E_), nW4};
    cj.j[5] = {(const float4*)Wv, (uint2*)(wh + 2 * E_ * E_), (uint2*)(wl + 2 * E_ * E_), nW4};
    cj.j[6] = {(const float4*)Wo, (uint2*)(wh + 3 * E_ * E_), (uint2*)(wl + 3 * E_ * E_), nW4};
    convert_all<<<dim3(nIn4 / 256, 7), 256>>>(cj);
    kpad_to_float<<<(B_ * S_ + 255) / 256, 256>>>(kpad, kpf, B_ * S_);

    // fused QKV projections (grid.z = 3)
    GemmJobs3 gq;
    gq.j[0] = {iqh, iql, wh + 0 * E_ * E_, wl + 0 * E_ * E_, bq, pqh, pql, nullptr, 0.125f};
    gq.j[1] = {ikh, ikl, wh + 1 * E_ * E_, wl + 1 * E_ * E_, bk, pkh, pkl, nullptr, 1.0f};
    gq.j[2] = {ivh, ivl, wh + 2 * E_ * E_, wl + 2 * E_ * E_, bv, pvh, pvl, nullptr, 1.0f};
    gemm_tc<0><<<dim3(M_ / 128, E_ / 128, 3), 256, G_SMEM>>>(gq);

    // flash attention
    dim3 fgrid(T_ / 128, H_, B_);
    flash_mma<<<fgrid, 256, FA_SMEM>>>(pqh, pql, pkh, pkl, pvh, pvl, amask, kpf, ch, cl);

    // output projection (fp32 out)
    GemmJobs3 go;
    go.j[0] = {ch, cl, wh + 3 * E_ * E_, wl + 3 * E_ * E_, bo, nullptr, nullptr, out, 1.0f};
    go.j[1] = go.j[0];
    go.j[2] = go.j[0];
    gemm_tc<1><<<dim3(M_ / 128, E_ / 128, 1), 256, G_SMEM>>>(go);
}

// round 7
// speedup vs baseline: 1.1791x; 1.1791x over previous
#include <cuda_runtime.h>
#include <cuda_bf16.h>
#include <cstdint>

// Problem constants (fixed shapes)
constexpr int T_ = 2048;
constexpr int S_ = 2048;
constexpr int B_ = 2;
constexpr int E_ = 1024;
constexpr int H_ = 16;
constexpr int D_ = 64;
constexpr int M_ = T_ * B_;   // 4096

// ---------------------------------------------------------------------------
// Scratch (__device__ globals; allocations forbidden)
// ---------------------------------------------------------------------------
__device__ __nv_bfloat16 g_iqh[M_ * E_], g_iql[M_ * E_];
__device__ __nv_bfloat16 g_ikh[M_ * E_], g_ikl[M_ * E_];
__device__ __nv_bfloat16 g_ivh[M_ * E_], g_ivl[M_ * E_];
__device__ __nv_bfloat16 g_wh[4][E_ * E_], g_wl[4][E_ * E_];
__device__ __nv_bfloat16 g_pqh[B_ * H_ * T_ * D_], g_pql[B_ * H_ * T_ * D_];
__device__ __nv_bfloat16 g_pkh[B_ * H_ * S_ * D_], g_pkl[B_ * H_ * S_ * D_];
__device__ __nv_bfloat16 g_pvh[B_ * H_ * S_ * D_], g_pvl[B_ * H_ * S_ * D_];
__device__ __nv_bfloat16 g_ch[M_ * E_], g_cl[M_ * E_];
__device__ float g_kpf[B_ * S_];

// ---------------------------------------------------------------------------
// PTX helpers (generic PTX only)
// ---------------------------------------------------------------------------
__device__ __forceinline__ uint32_t smem_u32(const void* p) {
    uint32_t a;
    asm("{ .reg .u64 t; cvta.to.shared.u64 t, %1; cvt.u32.u64 %0, t; }"
        : "=r"(a) : "l"(p));
    return a;
}
__device__ __forceinline__ void cp16(uint32_t dst, const void* src) {
    asm volatile("cp.async.cg.shared.global [%0], [%1], 16;" :: "r"(dst), "l"(src));
}
__device__ __forceinline__ void cp_commit() {
    asm volatile("cp.async.commit_group;" ::: "memory");
}
template <int N>
__device__ __forceinline__ void cp_wait() {
    asm volatile("cp.async.wait_group %0;" :: "n"(N) : "memory");
}
__device__ __forceinline__ void ldsm4(uint32_t& r0, uint32_t& r1, uint32_t& r2,
                                      uint32_t& r3, uint32_t addr) {
    asm volatile("ldmatrix.sync.aligned.m8n8.x4.shared.b16 {%0,%1,%2,%3}, [%4];"
                 : "=r"(r0), "=r"(r1), "=r"(r2), "=r"(r3) : "r"(addr));
}
__device__ __forceinline__ void ldsm4t(uint32_t* r, uint32_t addr) {
    asm volatile("ldmatrix.sync.aligned.m8n8.x4.trans.shared.b16 {%0,%1,%2,%3}, [%4];"
                 : "=r"(r[0]), "=r"(r[1]), "=r"(r[2]), "=r"(r[3]) : "r"(addr));
}
__device__ __forceinline__ void mma_bf16(float* c, const uint32_t* a,
                                         uint32_t b0, uint32_t b1) {
    asm volatile(
        "mma.sync.aligned.m16n8k16.row.col.f32.bf16.bf16.f32 "
        "{%0,%1,%2,%3}, {%4,%5,%6,%7}, {%8,%9}, {%0,%1,%2,%3};"
        : "+f"(c[0]), "+f"(c[1]), "+f"(c[2]), "+f"(c[3])
        : "r"(a[0]), "r"(a[1]), "r"(a[2]), "r"(a[3]), "r"(b0), "r"(b1));
}
__device__ __forceinline__ uint32_t packbf(float x, float y) {
    __nv_bfloat162 t = __floats2bfloat162_rn(x, y);
    return *reinterpret_cast<uint32_t*>(&t);
}
__device__ __forceinline__ float2 unpackbf(uint32_t u) {
    __nv_bfloat162 t = *reinterpret_cast<__nv_bfloat162*>(&u);
    return make_float2(__bfloat162float(t.x), __bfloat162float(t.y));
}

// ---------------------------------------------------------------------------
// Batched convert fp32 -> (bf16 hi, bf16 lo): 7 jobs in one launch
// ---------------------------------------------------------------------------
struct CvtJob { const float4* src; uint2* hi; uint2* lo; int n4; };
struct CvtJobs { CvtJob j[7]; };

__global__ void __launch_bounds__(256)
convert_all(CvtJobs jobs)
{
    const CvtJob jb = jobs.j[blockIdx.y];
    const int i = blockIdx.x * 256 + threadIdx.x;
    if (i >= jb.n4) return;
    float4 v = jb.src[i];
    __nv_bfloat16 h[4], l[4];
    float f[4] = {v.x, v.y, v.z, v.w};
    #pragma unroll
    for (int j = 0; j < 4; j++) {
        h[j] = __float2bfloat16(f[j]);
        l[j] = __float2bfloat16(f[j] - __bfloat162float(h[j]));
    }
    jb.hi[i] = *reinterpret_cast<uint2*>(h);
    jb.lo[i] = *reinterpret_cast<uint2*>(l);
}

__global__ void kpad_to_float(const unsigned char* __restrict__ kp,
                              float* __restrict__ out, int n)
{
    int i = blockIdx.x * 256 + threadIdx.x;
    if (i < n) out[i] = kp[i] ? -1e9f : 0.f;
}

// ---------------------------------------------------------------------------
// HMMA GEMM (unchanged from R6): tile 128x128, BK=32, 8 warps (warp 64x32),
// 3-term bf16 split, 2 CTAs/SM.
// ---------------------------------------------------------------------------
struct GemmJob {
    const __nv_bfloat16 *Ah, *Al, *Wh, *Wl;
    const float* bias;
    __nv_bfloat16 *Chi, *Clo;
    float* Cf;
    float scale;
};
struct GemmJobs3 { GemmJob j[3]; };

constexpr int G_STAGE = 32768;
constexpr int G_SMEM  = 2 * G_STAGE;   // 64 KB

__device__ __forceinline__ uint32_t sw_addr(int row, int byte_in_row) {
    uint32_t b = (uint32_t)(row * 64 + byte_in_row);
    return b ^ (((uint32_t)row & 3u) << 4);
}

__device__ __forceinline__ void g_load(
    uint32_t sdst, const GemmJob& jb, int bm, int bn, int k0, int tid)
{
    const __nv_bfloat16* srcs[4] = {jb.Ah, jb.Al, jb.Wh, jb.Wl};
    const int rbase[4] = {bm, bm, bn, bn};
    #pragma unroll
    for (int i = 0; i < 8; i++) {
        const int id = tid + i * 256;
        const int sub = id >> 9;
        const int lin = id & 511;
        const int row = lin >> 2, c = lin & 3;
        cp16(sdst + sub * 8192 + sw_addr(row, c * 16),
             srcs[sub] + (size_t)(rbase[sub] + row) * E_ + k0 + c * 8);
    }
}

template <int OUT_MODE>
__global__ void __launch_bounds__(256, 2)
gemm_tc(GemmJobs3 jobs)
{
    extern __shared__ char smem[];
    const uint32_t sbase = smem_u32(smem);
    const GemmJob jb = jobs.j[blockIdx.z];
    const int tid = threadIdx.x;
    const int warp = tid >> 5;
    const int lane = tid & 31;
    const int bm = blockIdx.x * 128;
    const int bn = blockIdx.y * 128;

    const int wm = (warp >> 2) * 64;
    const int wn = (warp & 3) * 32;

    float acc[4][4][4] = {};
    const int lrow = lane & 15;
    const int lseg = lane >> 4;

    g_load(sbase, jb, bm, bn, 0, tid);
    cp_commit();

    for (int chunk = 0; chunk < 32; chunk++) {
        const int s = chunk & 1;
        cp_wait<0>();
        __syncthreads();
        if (chunk < 31) {
            g_load(sbase + (s ^ 1) * G_STAGE, jb, bm, bn, (chunk + 1) * 32, tid);
            cp_commit();
        }
        const uint32_t st = sbase + s * G_STAGE;
        #pragma unroll
        for (int kk = 0; kk < 2; kk++) {
            const int c16 = (kk * 2 + lseg) * 16;
            uint32_t ah[4][4], al[4][4], bh[2][4], bl[2][4];
            #pragma unroll
            for (int mi = 0; mi < 4; mi++) {
                const uint32_t a = sw_addr(wm + mi * 16 + lrow, c16);
                ldsm4(ah[mi][0], ah[mi][1], ah[mi][2], ah[mi][3], st + a);
                ldsm4(al[mi][0], al[mi][1], al[mi][2], al[mi][3], st + 8192 + a);
            }
            #pragma unroll
            for (int nb = 0; nb < 2; nb++) {
                const uint32_t a = sw_addr(wn + nb * 16 + lrow, c16);
                ldsm4(bh[nb][0], bh[nb][1], bh[nb][2], bh[nb][3], st + 16384 + a);
                ldsm4(bl[nb][0], bl[nb][1], bl[nb][2], bl[nb][3], st + 24576 + a);
            }
            #pragma unroll
            for (int mi = 0; mi < 4; mi++) {
                #pragma unroll
                for (int ni = 0; ni < 4; ni++) {
                    const int nb = ni >> 1, hp = ni & 1;
                    mma_bf16(acc[mi][ni], ah[mi], bh[nb][hp], bh[nb][hp + 2]);
                    mma_bf16(acc[mi][ni], ah[mi], bl[nb][hp], bl[nb][hp + 2]);
                    mma_bf16(acc[mi][ni], al[mi], bh[nb][hp], bh[nb][hp + 2]);
                }
            }
        }
    }

    #pragma unroll
    for (int mi = 0; mi < 4; mi++) {
        #pragma unroll
        for (int ni = 0; ni < 4; ni++) {
            const int col = bn + wn + ni * 8 + (lane & 3) * 2;
            const float b0 = jb.bias[col], b1 = jb.bias[col + 1];
            #pragma unroll
            for (int half = 0; half < 2; half++) {
                const int m = bm + wm + mi * 16 + (lane >> 2) + half * 8;
                float ox = (acc[mi][ni][half * 2 + 0] + b0) * jb.scale;
                float oy = (acc[mi][ni][half * 2 + 1] + b1) * jb.scale;
                if (OUT_MODE == 0) {
                    const int t = m >> 1, b = m & 1;   // m = t*B + b, B=2
                    const int h = col >> 6, dd = col & 63;
                    const size_t idx = ((size_t)(b * H_ + h) * T_ + t) * D_ + dd;
                    uint32_t hp_ = packbf(ox, oy);
                    float2 hf = unpackbf(hp_);
                    uint32_t lp_ = packbf(ox - hf.x, oy - hf.y);
                    *(uint32_t*)&jb.Chi[idx] = hp_;
                    *(uint32_t*)&jb.Clo[idx] = lp_;
                } else {
                    *(float2*)&jb.Cf[(size_t)m * E_ + col] = make_float2(ox, oy);
                }
            }
        }
    }
}

// ---------------------------------------------------------------------------
// Flash attention via HMMA, 3-term hi/lo split (R5 pipeline structure).
// CTA: 64 q-rows of one (b,h); 4 warps x 16 rows; 128 threads.
// smem: Q hi/lo 16KB + 2 stages x (K/V 32KB) = 80.5KB  -> 2 CTAs/SM.
// Q fragments cached in registers; mask + kpad read direct from global;
// row-sum l via fp32 FMA + shfl (off the tensor pipe).
// ---------------------------------------------------------------------------
constexpr uint32_t FA_OFF_QL = 8192;
constexpr uint32_t FA_OFF_ST = 16384;
constexpr uint32_t FA_ST_B   = 32768;
constexpr int FA_SMEM = 16384 + 2 * 32768;   // 81920

__device__ __forceinline__ uint32_t fa_off(int row, int chunk) {
    return (uint32_t)(row * 128 + ((chunk ^ (row & 7)) << 4));
}

__device__ __forceinline__ void fa_load_stage(
    uint32_t sbase, int stage,
    const __nv_bfloat16* __restrict__ kh, const __nv_bfloat16* __restrict__ kl,
    const __nv_bfloat16* __restrict__ vh, const __nv_bfloat16* __restrict__ vl,
    int s0, int tid)
{
    const __nv_bfloat16* srcs[4] = {kh, kl, vh, vl};
    #pragma unroll
    for (int i = 0; i < 16; i++) {
        const int id = tid + i * 128;
        const int sub = id >> 9;
        const int lin = id & 511;
        const int row = lin >> 3;
        const int c   = lin & 7;
        cp16(sbase + FA_OFF_ST + stage * FA_ST_B + sub * 8192 + fa_off(row, c),
             srcs[sub] + (size_t)(s0 + row) * D_ + c * 8);
    }
}

__global__ void __launch_bounds__(128, 2)
flash_mma(const __nv_bfloat16* __restrict__ qh_g, const __nv_bfloat16* __restrict__ ql_g,
          const __nv_bfloat16* __restrict__ kh_g, const __nv_bfloat16* __restrict__ kl_g,
          const __nv_bfloat16* __restrict__ vh_g, const __nv_bfloat16* __restrict__ vl_g,
          const float* __restrict__ maskg, const float* __restrict__ kpf_g,
          __nv_bfloat16* __restrict__ ch, __nv_bfloat16* __restrict__ cl)
{
    extern __shared__ char smem[];
    const uint32_t sbase = smem_u32(smem);
    const int tid = threadIdx.x;
    const int lane = tid & 31;
    const int warp = tid >> 5;
    const int t0 = blockIdx.x * 64;
    const int h = blockIdx.y;
    const int b = blockIdx.z;

    const size_t hoff = (size_t)(b * H_ + h);
    const __nv_bfloat16* qh = qh_g + (hoff * T_ + t0) * D_;
    const __nv_bfloat16* ql = ql_g + (hoff * T_ + t0) * D_;
    const __nv_bfloat16* kh = kh_g + hoff * S_ * D_;
    const __nv_bfloat16* kl = kl_g + hoff * S_ * D_;
    const __nv_bfloat16* vh = vh_g + hoff * S_ * D_;
    const __nv_bfloat16* vl = vl_g + hoff * S_ * D_;
    const float* kpf = kpf_g + b * S_;

    // Q tile load (64x64 hi/lo) + stage 0, one commit group
    #pragma unroll
    for (int i = 0; i < 8; i++) {
        const int id = tid + i * 128;
        const int sub = id >> 9;
        const int lin = id & 511;
        const int row = lin >> 3;
        const int c   = lin & 7;
        cp16(sbase + sub * FA_OFF_QL + fa_off(row, c),
             (sub ? ql : qh) + (size_t)row * D_ + c * 8);
    }
    fa_load_stage(sbase, 0, kh, kl, vh, vl, 0, tid);
    cp_commit();

    const int wm = warp * 16;
    const int lrow = lane & 15;
    const int lseg = lane >> 4;
    const int qr = lane >> 2;
    const int qc = (lane & 3) * 2;

    float acc[8][4] = {};
    float l0 = 0.f, l1 = 0.f;
    float m0 = -1e30f, m1 = -1e30f;
    uint32_t qah[4][4], qal[4][4];   // cached Q fragments (hi/lo), per k16 step

    const float* mrow0_base = maskg + (size_t)(t0 + wm + qr) * S_ + qc;
    const float* mrow1_base = mrow0_base + 8 * S_;

    for (int tile = 0; tile < 32; tile++) {
        const int stg = tile & 1;
        cp_wait<0>();
        __syncthreads();
        if (tile == 0) {
            // cache Q fragments once
            #pragma unroll
            for (int kk = 0; kk < 4; kk++) {
                const uint32_t a = fa_off(wm + lrow, kk * 2 + lseg);
                ldsm4(qah[kk][0], qah[kk][1], qah[kk][2], qah[kk][3], sbase + a);
                ldsm4(qal[kk][0], qal[kk][1], qal[kk][2], qal[kk][3],
                      sbase + FA_OFF_QL + a);
            }
        }
        if (tile < 31) {
            fa_load_stage(sbase, stg ^ 1, kh, kl, vh, vl, (tile + 1) * 64, tid);
            cp_commit();
        }

        const uint32_t stk = sbase + FA_OFF_ST + stg * FA_ST_B;

        // ---- scores: S = Qh Kh + Qh Kl + Ql Kh ----
        float sc[8][4];
        #pragma unroll
        for (int j = 0; j < 8; j++) {
            sc[j][0] = 0.f; sc[j][1] = 0.f; sc[j][2] = 0.f; sc[j][3] = 0.f;
        }
        #pragma unroll
        for (int kk = 0; kk < 4; kk++) {
            #pragma unroll
            for (int nb = 0; nb < 4; nb++) {
                uint32_t bh[4], bl[4];
                ldsm4(bh[0], bh[1], bh[2], bh[3],
                      stk + fa_off(nb * 16 + lrow, kk * 2 + lseg));
                ldsm4(bl[0], bl[1], bl[2], bl[3],
                      stk + 8192 + fa_off(nb * 16 + lrow, kk * 2 + lseg));
                #pragma unroll
                for (int hp = 0; hp < 2; hp++) {
                    float* sf = sc[nb * 2 + hp];
                    mma_bf16(sf, qah[kk], bh[hp], bh[hp + 2]);
                    mma_bf16(sf, qah[kk], bl[hp], bl[hp + 2]);
                    mma_bf16(sf, qal[kk], bh[hp], bh[hp + 2]);
                }
            }
        }

        // ---- masks (direct global; L2-hot across the 32 (b,h) CTAs) ----
        const int scol = tile * 64;
        #pragma unroll
        for (int j = 0; j < 8; j++) {
            float2 k2 = *(const float2*)&kpf[scol + j * 8 + qc];
            float2 a0 = *(const float2*)&mrow0_base[scol + j * 8];
            float2 a1 = *(const float2*)&mrow1_base[scol + j * 8];
            sc[j][0] += a0.x + k2.x; sc[j][1] += a0.y + k2.y;
            sc[j][2] += a1.x + k2.x; sc[j][3] += a1.y + k2.y;
        }

        // ---- online softmax ----
        float tm0 = -1e30f, tm1 = -1e30f;
        #pragma unroll
        for (int j = 0; j < 8; j++) {
            tm0 = fmaxf(tm0, fmaxf(sc[j][0], sc[j][1]));
            tm1 = fmaxf(tm1, fmaxf(sc[j][2], sc[j][3]));
        }
        tm0 = fmaxf(tm0, __shfl_xor_sync(0xffffffffu, tm0, 1, 4));
        tm0 = fmaxf(tm0, __shfl_xor_sync(0xffffffffu, tm0, 2, 4));
        tm1 = fmaxf(tm1, __shfl_xor_sync(0xffffffffu, tm1, 1, 4));
        tm1 = fmaxf(tm1, __shfl_xor_sync(0xffffffffu, tm1, 2, 4));
        const float mn0 = fmaxf(m0, tm0), mn1 = fmaxf(m1, tm1);
        const float cr0 = __expf(m0 - mn0), cr1 = __expf(m1 - mn1);
        m0 = mn0; m1 = mn1;
        float rs0 = 0.f, rs1 = 0.f;
        #pragma unroll
        for (int j = 0; j < 8; j++) {
            sc[j][0] = __expf(sc[j][0] - mn0);
            sc[j][1] = __expf(sc[j][1] - mn0);
            sc[j][2] = __expf(sc[j][2] - mn1);
            sc[j][3] = __expf(sc[j][3] - mn1);
            rs0 += sc[j][0] + sc[j][1];
            rs1 += sc[j][2] + sc[j][3];
        }
        rs0 += __shfl_xor_sync(0xffffffffu, rs0, 1, 4);
        rs0 += __shfl_xor_sync(0xffffffffu, rs0, 2, 4);
        rs1 += __shfl_xor_sync(0xffffffffu, rs1, 1, 4);
        rs1 += __shfl_xor_sync(0xffffffffu, rs1, 2, 4);
        l0 = l0 * cr0 + rs0;
        l1 = l1 * cr1 + rs1;
        #pragma unroll
        for (int j = 0; j < 8; j++) {
            acc[j][0] *= cr0; acc[j][1] *= cr0;
            acc[j][2] *= cr1; acc[j][3] *= cr1;
        }

        // ---- PV: O += Ph Vh + Ph Vl + Pl Vh ----
        #pragma unroll
        for (int kk = 0; kk < 4; kk++) {
            const int j0 = 2 * kk, j1 = j0 + 1;
            uint32_t ph[4], pl[4];
            {
                float px[8] = {sc[j0][0], sc[j0][1], sc[j0][2], sc[j0][3],
                               sc[j1][0], sc[j1][1], sc[j1][2], sc[j1][3]};
                #pragma unroll
                for (int q = 0; q < 4; q++) {
                    uint32_t hp_ = packbf(px[2 * q], px[2 * q + 1]);
                    float2 hf = unpackbf(hp_);
                    ph[q] = hp_;
                    pl[q] = packbf(px[2 * q] - hf.x, px[2 * q + 1] - hf.y);
                }
            }
            #pragma unroll
            for (int ng = 0; ng < 4; ng++) {
                uint32_t v4[4], w4[4];
                ldsm4t(v4, stk + 16384 + fa_off(kk * 16 + lrow, ng * 2 + lseg));
                ldsm4t(w4, stk + 24576 + fa_off(kk * 16 + lrow, ng * 2 + lseg));
                mma_bf16(acc[ng * 2 + 0], ph, v4[0], v4[1]);
                mma_bf16(acc[ng * 2 + 0], ph, w4[0], w4[1]);
                mma_bf16(acc[ng * 2 + 0], pl, v4[0], v4[1]);
                mma_bf16(acc[ng * 2 + 1], ph, v4[2], v4[3]);
                mma_bf16(acc[ng * 2 + 1], ph, w4[2], w4[3]);
                mma_bf16(acc[ng * 2 + 1], pl, v4[2], v4[3]);
            }
        }
    }

    // ---- epilogue: normalize, write ctx bf16 hi/lo [t*B+b][E] ----
    const float inv0 = 1.f / l0, inv1 = 1.f / l1;
    const int r0 = t0 + wm + qr, r1 = r0 + 8;
    #pragma unroll
    for (int j = 0; j < 8; j++) {
        const int col = h * D_ + j * 8 + qc;
        {
            float x = acc[j][0] * inv0, y = acc[j][1] * inv0;
            uint32_t hp_ = packbf(x, y);
            float2 hf = unpackbf(hp_);
            uint32_t lp_ = packbf(x - hf.x, y - hf.y);
            const size_t idx = ((size_t)r0 * B_ + b) * E_ + col;
            *(uint32_t*)&ch[idx] = hp_;
            *(uint32_t*)&cl[idx] = lp_;
        }
        {
            float x = acc[j][2] * inv1, y = acc[j][3] * inv1;
            uint32_t hp_ = packbf(x, y);
            float2 hf = unpackbf(hp_);
            uint32_t lp_ = packbf(x - hf.x, y - hf.y);
            const size_t idx = ((size_t)r1 * B_ + b) * E_ + col;
            *(uint32_t*)&ch[idx] = hp_;
            *(uint32_t*)&cl[idx] = lp_;
        }
    }
}

// ---------------------------------------------------------------------------
// Launch
// ---------------------------------------------------------------------------
extern "C" void kernel_launch(void* const* d_in, const int* in_sizes, int n_in,
                              void* d_out, int out_size)
{
    const float* query = (const float*)d_in[0];
    const float* key   = (const float*)d_in[1];
    const float* value = (const float*)d_in[2];
    const float* amask = (const float*)d_in[3];
    const unsigned char* kpad = (const unsigned char*)d_in[4];
    const float* Wq = (const float*)d_in[5];
    const float* bq = (const float*)d_in[6];
    const float* Wk = (const float*)d_in[7];
    const float* bk = (const float*)d_in[8];
    const float* Wv = (const float*)d_in[9];
    const float* bv = (const float*)d_in[10];
    const float* Wo = (const float*)d_in[11];
    const float* bo = (const float*)d_in[12];
    float* out = (float*)d_out;

    __nv_bfloat16 *iqh, *iql, *ikh, *ikl, *ivh, *ivl, *wh, *wl;
    __nv_bfloat16 *pqh, *pql, *pkh, *pkl, *pvh, *pvl, *ch, *cl;
    float* kpf;
    cudaGetSymbolAddress((void**)&iqh, g_iqh); cudaGetSymbolAddress((void**)&iql, g_iql);
    cudaGetSymbolAddress((void**)&ikh, g_ikh); cudaGetSymbolAddress((void**)&ikl, g_ikl);
    cudaGetSymbolAddress((void**)&ivh, g_ivh); cudaGetSymbolAddress((void**)&ivl, g_ivl);
    cudaGetSymbolAddress((void**)&wh, g_wh);   cudaGetSymbolAddress((void**)&wl, g_wl);
    cudaGetSymbolAddress((void**)&pqh, g_pqh); cudaGetSymbolAddress((void**)&pql, g_pql);
    cudaGetSymbolAddress((void**)&pkh, g_pkh); cudaGetSymbolAddress((void**)&pkl, g_pkl);
    cudaGetSymbolAddress((void**)&pvh, g_pvh); cudaGetSymbolAddress((void**)&pvl, g_pvl);
    cudaGetSymbolAddress((void**)&ch, g_ch);   cudaGetSymbolAddress((void**)&cl, g_cl);
    cudaGetSymbolAddress((void**)&kpf, g_kpf);

    cudaFuncSetAttribute(gemm_tc<0>, cudaFuncAttributeMaxDynamicSharedMemorySize, G_SMEM);
    cudaFuncSetAttribute(gemm_tc<1>, cudaFuncAttributeMaxDynamicSharedMemorySize, G_SMEM);
    cudaFuncSetAttribute(flash_mma, cudaFuncAttributeMaxDynamicSharedMemorySize, FA_SMEM);

    const int nIn4 = M_ * E_ / 4;
    const int nW4  = E_ * E_ / 4;

    CvtJobs cj;
    cj.j[0] = {(const float4*)query, (uint2*)iqh, (uint2*)iql, nIn4};
    cj.j[1] = {(const float4*)key,   (uint2*)ikh, (uint2*)ikl, nIn4};
    cj.j[2] = {(const float4*)value, (uint2*)ivh, (uint2*)ivl, nIn4};
    cj.j[3] = {(const float4*)Wq, (uint2*)(wh + 0 * E_ * E_), (uint2*)(wl + 0 * E_ * E_), nW4};
    cj.j[4] = {(const float4*)Wk, (uint2*)(wh + 1 * E_ * E_), (uint2*)(wl + 1 * E_ * E_), nW4};
    cj.j[5] = {(const float4*)Wv, (uint2*)(wh + 2 * E_ * E_), (uint2*)(wl + 2 * E_ * E_), nW4};
    cj.j[6] = {(const float4*)Wo, (uint2*)(wh + 3 * E_ * E_), (uint2*)(wl + 3 * E_ * E_), nW4};
    convert_all<<<dim3(nIn4 / 256, 7), 256>>>(cj);
    kpad_to_float<<<(B_ * S_ + 255) / 256, 256>>>(kpad, kpf, B_ * S_);

    // fused QKV projections (grid.z = 3)
    GemmJobs3 gq;
    gq.j[0] = {iqh, iql, wh + 0 * E_ * E_, wl + 0 * E_ * E_, bq, pqh, pql, nullptr, 0.125f};
    gq.j[1] = {ikh, ikl, wh + 1 * E_ * E_, wl + 1 * E_ * E_, bk, pkh, pkl, nullptr, 1.0f};
    gq.j[2] = {ivh, ivl, wh + 2 * E_ * E_, wl + 2 * E_ * E_, bv, pvh, pvl, nullptr, 1.0f};
    gemm_tc<0><<<dim3(M_ / 128, E_ / 128, 3), 256, G_SMEM>>>(gq);

    // flash attention: 64-row CTAs, 128 threads, 2 CTAs/SM
    dim3 fgrid(T_ / 64, H_, B_);
    flash_mma<<<fgrid, 128, FA_SMEM>>>(pqh, pql, pkh, pkl, pvh, pvl, amask, kpf, ch, cl);

    // output projection (fp32 out)
    GemmJobs3 go;
    go.j[0] = {ch, cl, wh + 3 * E_ * E_, wl + 3 * E_ * E_, bo, nullptr, nullptr, out, 1.0f};
    go.j[1] = go.j[0];
    go.j[2] = go.j[0];
    gemm_tc<1><<<dim3(M_ / 128, E_ / 128, 1), 256, G_SMEM>>>(go);
}

// round 8
// speedup vs baseline: 1.1851x; 1.0050x over previous
#include <cuda_runtime.h>
#include <cuda_bf16.h>
#include <cstdint>

// Problem constants (fixed shapes)
constexpr int T_ = 2048;
constexpr int S_ = 2048;
constexpr int B_ = 2;
constexpr int E_ = 1024;
constexpr int H_ = 16;
constexpr int D_ = 64;
constexpr int M_ = T_ * B_;   // 4096

// ---------------------------------------------------------------------------
// Scratch (__device__ globals; allocations forbidden)
// ---------------------------------------------------------------------------
__device__ __nv_bfloat16 g_iqh[M_ * E_], g_iql[M_ * E_];
__device__ __nv_bfloat16 g_ikh[M_ * E_], g_ikl[M_ * E_];
__device__ __nv_bfloat16 g_ivh[M_ * E_], g_ivl[M_ * E_];
__device__ __nv_bfloat16 g_wh[4][E_ * E_], g_wl[4][E_ * E_];
__device__ __nv_bfloat16 g_pqh[B_ * H_ * T_ * D_], g_pql[B_ * H_ * T_ * D_];
__device__ __nv_bfloat16 g_pkh[B_ * H_ * S_ * D_], g_pkl[B_ * H_ * S_ * D_];
__device__ __nv_bfloat16 g_pvh[B_ * H_ * S_ * D_], g_pvl[B_ * H_ * S_ * D_];
__device__ __nv_bfloat16 g_ch[M_ * E_], g_cl[M_ * E_];
__device__ float g_kpf[B_ * S_];

// ---------------------------------------------------------------------------
// PTX helpers (generic PTX only)
// ---------------------------------------------------------------------------
__device__ __forceinline__ uint32_t smem_u32(const void* p) {
    uint32_t a;
    asm("{ .reg .u64 t; cvta.to.shared.u64 t, %1; cvt.u32.u64 %0, t; }"
        : "=r"(a) : "l"(p));
    return a;
}
__device__ __forceinline__ void cp16(uint32_t dst, const void* src) {
    asm volatile("cp.async.cg.shared.global [%0], [%1], 16;" :: "r"(dst), "l"(src));
}
__device__ __forceinline__ void cp_commit() {
    asm volatile("cp.async.commit_group;" ::: "memory");
}
template <int N>
__device__ __forceinline__ void cp_wait() {
    asm volatile("cp.async.wait_group %0;" :: "n"(N) : "memory");
}
__device__ __forceinline__ void ldsm4(uint32_t& r0, uint32_t& r1, uint32_t& r2,
                                      uint32_t& r3, uint32_t addr) {
    asm volatile("ldmatrix.sync.aligned.m8n8.x4.shared.b16 {%0,%1,%2,%3}, [%4];"
                 : "=r"(r0), "=r"(r1), "=r"(r2), "=r"(r3) : "r"(addr));
}
__device__ __forceinline__ void ldsm4t(uint32_t* r, uint32_t addr) {
    asm volatile("ldmatrix.sync.aligned.m8n8.x4.trans.shared.b16 {%0,%1,%2,%3}, [%4];"
                 : "=r"(r[0]), "=r"(r[1]), "=r"(r[2]), "=r"(r[3]) : "r"(addr));
}
__device__ __forceinline__ void mma_bf16(float* c, const uint32_t* a,
                                         uint32_t b0, uint32_t b1) {
    asm volatile(
        "mma.sync.aligned.m16n8k16.row.col.f32.bf16.bf16.f32 "
        "{%0,%1,%2,%3}, {%4,%5,%6,%7}, {%8,%9}, {%0,%1,%2,%3};"
        : "+f"(c[0]), "+f"(c[1]), "+f"(c[2]), "+f"(c[3])
        : "r"(a[0]), "r"(a[1]), "r"(a[2]), "r"(a[3]), "r"(b0), "r"(b1));
}
__device__ __forceinline__ uint32_t packbf(float x, float y) {
    __nv_bfloat162 t = __floats2bfloat162_rn(x, y);
    return *reinterpret_cast<uint32_t*>(&t);
}
__device__ __forceinline__ float2 unpackbf(uint32_t u) {
    __nv_bfloat162 t = *reinterpret_cast<__nv_bfloat162*>(&u);
    return make_float2(__bfloat162float(t.x), __bfloat162float(t.y));
}

// ---------------------------------------------------------------------------
// Batched convert fp32 -> (bf16 hi, bf16 lo): 7 jobs in one launch
// ---------------------------------------------------------------------------
struct CvtJob { const float4* src; uint2* hi; uint2* lo; int n4; };
struct CvtJobs { CvtJob j[7]; };

__global__ void __launch_bounds__(256)
convert_all(CvtJobs jobs)
{
    const CvtJob jb = jobs.j[blockIdx.y];
    const int i = blockIdx.x * 256 + threadIdx.x;
    if (i >= jb.n4) return;
    float4 v = jb.src[i];
    __nv_bfloat16 h[4], l[4];
    float f[4] = {v.x, v.y, v.z, v.w};
    #pragma unroll
    for (int j = 0; j < 4; j++) {
        h[j] = __float2bfloat16(f[j]);
        l[j] = __float2bfloat16(f[j] - __bfloat162float(h[j]));
    }
    jb.hi[i] = *reinterpret_cast<uint2*>(h);
    jb.lo[i] = *reinterpret_cast<uint2*>(l);
}

__global__ void kpad_to_float(const unsigned char* __restrict__ kp,
                              float* __restrict__ out, int n)
{
    int i = blockIdx.x * 256 + threadIdx.x;
    if (i < n) out[i] = kp[i] ? -1e9f : 0.f;
}

// ---------------------------------------------------------------------------
// HMMA GEMM: tile 128x128, BK=32, 8 warps (warp 64x32), 3-term bf16 split,
// 2 CTAs/SM. MMA issue is TERM-MAJOR: all 16 accumulators get term0, then
// term1, then term2 -> same-accumulator dependency distance = 16 MMAs.
// Per-accumulator addition order unchanged (hh, hl, lh) -> bit-identical.
// ---------------------------------------------------------------------------
struct GemmJob {
    const __nv_bfloat16 *Ah, *Al, *Wh, *Wl;
    const float* bias;
    __nv_bfloat16 *Chi, *Clo;
    float* Cf;
    float scale;
};
struct GemmJobs3 { GemmJob j[3]; };

constexpr int G_STAGE = 32768;
constexpr int G_SMEM  = 2 * G_STAGE;   // 64 KB

__device__ __forceinline__ uint32_t sw_addr(int row, int byte_in_row) {
    uint32_t b = (uint32_t)(row * 64 + byte_in_row);
    return b ^ (((uint32_t)row & 3u) << 4);
}

__device__ __forceinline__ void g_load(
    uint32_t sdst, const GemmJob& jb, int bm, int bn, int k0, int tid)
{
    const __nv_bfloat16* srcs[4] = {jb.Ah, jb.Al, jb.Wh, jb.Wl};
    const int rbase[4] = {bm, bm, bn, bn};
    #pragma unroll
    for (int i = 0; i < 8; i++) {
        const int id = tid + i * 256;
        const int sub = id >> 9;
        const int lin = id & 511;
        const int row = lin >> 2, c = lin & 3;
        cp16(sdst + sub * 8192 + sw_addr(row, c * 16),
             srcs[sub] + (size_t)(rbase[sub] + row) * E_ + k0 + c * 8);
    }
}

template <int OUT_MODE>
__global__ void __launch_bounds__(256, 2)
gemm_tc(GemmJobs3 jobs)
{
    extern __shared__ char smem[];
    const uint32_t sbase = smem_u32(smem);
    const GemmJob jb = jobs.j[blockIdx.z];
    const int tid = threadIdx.x;
    const int warp = tid >> 5;
    const int lane = tid & 31;
    const int bm = blockIdx.x * 128;
    const int bn = blockIdx.y * 128;

    const int wm = (warp >> 2) * 64;
    const int wn = (warp & 3) * 32;

    float acc[4][4][4] = {};
    const int lrow = lane & 15;
    const int lseg = lane >> 4;

    g_load(sbase, jb, bm, bn, 0, tid);
    cp_commit();

    for (int chunk = 0; chunk < 32; chunk++) {
        const int s = chunk & 1;
        cp_wait<0>();
        __syncthreads();
        if (chunk < 31) {
            g_load(sbase + (s ^ 1) * G_STAGE, jb, bm, bn, (chunk + 1) * 32, tid);
            cp_commit();
        }
        const uint32_t st = sbase + s * G_STAGE;
        #pragma unroll
        for (int kk = 0; kk < 2; kk++) {
            const int c16 = (kk * 2 + lseg) * 16;
            uint32_t ah[4][4], al[4][4], bh[2][4], bl[2][4];
            #pragma unroll
            for (int mi = 0; mi < 4; mi++) {
                const uint32_t a = sw_addr(wm + mi * 16 + lrow, c16);
                ldsm4(ah[mi][0], ah[mi][1], ah[mi][2], ah[mi][3], st + a);
                ldsm4(al[mi][0], al[mi][1], al[mi][2], al[mi][3], st + 8192 + a);
            }
            #pragma unroll
            for (int nb = 0; nb < 2; nb++) {
                const uint32_t a = sw_addr(wn + nb * 16 + lrow, c16);
                ldsm4(bh[nb][0], bh[nb][1], bh[nb][2], bh[nb][3], st + 16384 + a);
                ldsm4(bl[nb][0], bl[nb][1], bl[nb][2], bl[nb][3], st + 24576 + a);
            }
            // term-major: same-acc dependency distance = 16 MMAs
            #pragma unroll
            for (int term = 0; term < 3; term++) {
                #pragma unroll
                for (int mi = 0; mi < 4; mi++) {
                    #pragma unroll
                    for (int ni = 0; ni < 4; ni++) {
                        const int nb = ni >> 1, hp = ni & 1;
                        if (term == 0)
                            mma_bf16(acc[mi][ni], ah[mi], bh[nb][hp], bh[nb][hp + 2]);
                        else if (term == 1)
                            mma_bf16(acc[mi][ni], ah[mi], bl[nb][hp], bl[nb][hp + 2]);
                        else
                            mma_bf16(acc[mi][ni], al[mi], bh[nb][hp], bh[nb][hp + 2]);
                    }
                }
            }
        }
    }

    #pragma unroll
    for (int mi = 0; mi < 4; mi++) {
        #pragma unroll
        for (int ni = 0; ni < 4; ni++) {
            const int col = bn + wn + ni * 8 + (lane & 3) * 2;
            const float b0 = jb.bias[col], b1 = jb.bias[col + 1];
            #pragma unroll
            for (int half = 0; half < 2; half++) {
                const int m = bm + wm + mi * 16 + (lane >> 2) + half * 8;
                float ox = (acc[mi][ni][half * 2 + 0] + b0) * jb.scale;
                float oy = (acc[mi][ni][half * 2 + 1] + b1) * jb.scale;
                if (OUT_MODE == 0) {
                    const int t = m >> 1, b = m & 1;   // m = t*B + b, B=2
                    const int h = col >> 6, dd = col & 63;
                    const size_t idx = ((size_t)(b * H_ + h) * T_ + t) * D_ + dd;
                    uint32_t hp_ = packbf(ox, oy);
                    float2 hf = unpackbf(hp_);
                    uint32_t lp_ = packbf(ox - hf.x, oy - hf.y);
                    *(uint32_t*)&jb.Chi[idx] = hp_;
                    *(uint32_t*)&jb.Clo[idx] = lp_;
                } else {
                    *(float2*)&jb.Cf[(size_t)m * E_ + col] = make_float2(ox, oy);
                }
            }
        }
    }
}

// ---------------------------------------------------------------------------
// Flash attention via HMMA, 3-term hi/lo split.
// CTA: 64 q-rows of one (b,h); 4 warps x 16 rows; 128 threads; 2 CTAs/SM.
// QK and PV issue MMAs term-major over PAIRS of 16-col blocks ->
// same-accumulator dependency distance = 4 MMAs (was 1).
// ---------------------------------------------------------------------------
constexpr uint32_t FA_OFF_QL = 8192;
constexpr uint32_t FA_OFF_ST = 16384;
constexpr uint32_t FA_ST_B   = 32768;
constexpr int FA_SMEM = 16384 + 2 * 32768;   // 81920

__device__ __forceinline__ uint32_t fa_off(int row, int chunk) {
    return (uint32_t)(row * 128 + ((chunk ^ (row & 7)) << 4));
}

__device__ __forceinline__ void fa_load_stage(
    uint32_t sbase, int stage,
    const __nv_bfloat16* __restrict__ kh, const __nv_bfloat16* __restrict__ kl,
    const __nv_bfloat16* __restrict__ vh, const __nv_bfloat16* __restrict__ vl,
    int s0, int tid)
{
    const __nv_bfloat16* srcs[4] = {kh, kl, vh, vl};
    #pragma unroll
    for (int i = 0; i < 16; i++) {
        const int id = tid + i * 128;
        const int sub = id >> 9;
        const int lin = id & 511;
        const int row = lin >> 3;
        const int c   = lin & 7;
        cp16(sbase + FA_OFF_ST + stage * FA_ST_B + sub * 8192 + fa_off(row, c),
             srcs[sub] + (size_t)(s0 + row) * D_ + c * 8);
    }
}

__global__ void __launch_bounds__(128, 2)
flash_mma(const __nv_bfloat16* __restrict__ qh_g, const __nv_bfloat16* __restrict__ ql_g,
          const __nv_bfloat16* __restrict__ kh_g, const __nv_bfloat16* __restrict__ kl_g,
          const __nv_bfloat16* __restrict__ vh_g, const __nv_bfloat16* __restrict__ vl_g,
          const float* __restrict__ maskg, const float* __restrict__ kpf_g,
          __nv_bfloat16* __restrict__ ch, __nv_bfloat16* __restrict__ cl)
{
    extern __shared__ char smem[];
    const uint32_t sbase = smem_u32(smem);
    const int tid = threadIdx.x;
    const int lane = tid & 31;
    const int warp = tid >> 5;
    const int t0 = blockIdx.x * 64;
    const int h = blockIdx.y;
    const int b = blockIdx.z;

    const size_t hoff = (size_t)(b * H_ + h);
    const __nv_bfloat16* qh = qh_g + (hoff * T_ + t0) * D_;
    const __nv_bfloat16* ql = ql_g + (hoff * T_ + t0) * D_;
    const __nv_bfloat16* kh = kh_g + hoff * S_ * D_;
    const __nv_bfloat16* kl = kl_g + hoff * S_ * D_;
    const __nv_bfloat16* vh = vh_g + hoff * S_ * D_;
    const __nv_bfloat16* vl = vl_g + hoff * S_ * D_;
    const float* kpf = kpf_g + b * S_;

    // Q tile load (64x64 hi/lo) + stage 0, one commit group
    #pragma unroll
    for (int i = 0; i < 8; i++) {
        const int id = tid + i * 128;
        const int sub = id >> 9;
        const int lin = id & 511;
        const int row = lin >> 3;
        const int c   = lin & 7;
        cp16(sbase + sub * FA_OFF_QL + fa_off(row, c),
             (sub ? ql : qh) + (size_t)row * D_ + c * 8);
    }
    fa_load_stage(sbase, 0, kh, kl, vh, vl, 0, tid);
    cp_commit();

    const int wm = warp * 16;
    const int lrow = lane & 15;
    const int lseg = lane >> 4;
    const int qr = lane >> 2;
    const int qc = (lane & 3) * 2;

    float acc[8][4] = {};
    float l0 = 0.f, l1 = 0.f;
    float m0 = -1e30f, m1 = -1e30f;
    uint32_t qah[4][4], qal[4][4];   // cached Q fragments (hi/lo), per k16 step

    const float* mrow0_base = maskg + (size_t)(t0 + wm + qr) * S_ + qc;
    const float* mrow1_base = mrow0_base + 8 * S_;

    for (int tile = 0; tile < 32; tile++) {
        const int stg = tile & 1;
        cp_wait<0>();
        __syncthreads();
        if (tile == 0) {
            #pragma unroll
            for (int kk = 0; kk < 4; kk++) {
                const uint32_t a = fa_off(wm + lrow, kk * 2 + lseg);
                ldsm4(qah[kk][0], qah[kk][1], qah[kk][2], qah[kk][3], sbase + a);
                ldsm4(qal[kk][0], qal[kk][1], qal[kk][2], qal[kk][3],
                      sbase + FA_OFF_QL + a);
            }
        }
        if (tile < 31) {
            fa_load_stage(sbase, stg ^ 1, kh, kl, vh, vl, (tile + 1) * 64, tid);
            cp_commit();
        }

        const uint32_t stk = sbase + FA_OFF_ST + stg * FA_ST_B;

        // ---- scores: S = Qh Kh + Qh Kl + Ql Kh, term-major over nb pairs ----
        float sc[8][4];
        #pragma unroll
        for (int j = 0; j < 8; j++) {
            sc[j][0] = 0.f; sc[j][1] = 0.f; sc[j][2] = 0.f; sc[j][3] = 0.f;
        }
        #pragma unroll
        for (int kk = 0; kk < 4; kk++) {
            #pragma unroll
            for (int nbp = 0; nbp < 2; nbp++) {
                uint32_t bh[2][4], bl[2][4];
                #pragma unroll
                for (int p = 0; p < 2; p++) {
                    const int nb = nbp * 2 + p;
                    const uint32_t a = fa_off(nb * 16 + lrow, kk * 2 + lseg);
                    ldsm4(bh[p][0], bh[p][1], bh[p][2], bh[p][3], stk + a);
                    ldsm4(bl[p][0], bl[p][1], bl[p][2], bl[p][3], stk + 8192 + a);
                }
                #pragma unroll
                for (int term = 0; term < 3; term++) {
                    #pragma unroll
                    for (int p = 0; p < 2; p++) {
                        const int nb = nbp * 2 + p;
                        #pragma unroll
                        for (int hp = 0; hp < 2; hp++) {
                            float* sf = sc[nb * 2 + hp];
                            if (term == 0)
                                mma_bf16(sf, qah[kk], bh[p][hp], bh[p][hp + 2]);
                            else if (term == 1)
                                mma_bf16(sf, qah[kk], bl[p][hp], bl[p][hp + 2]);
                            else
                                mma_bf16(sf, qal[kk], bh[p][hp], bh[p][hp + 2]);
                        }
                    }
                }
            }
        }

        // ---- masks (direct global; L2-hot) ----
        const int scol = tile * 64;
        #pragma unroll
        for (int j = 0; j < 8; j++) {
            float2 k2 = *(const float2*)&kpf[scol + j * 8 + qc];
            float2 a0 = *(const float2*)&mrow0_base[scol + j * 8];
            float2 a1 = *(const float2*)&mrow1_base[scol + j * 8];
            sc[j][0] += a0.x + k2.x; sc[j][1] += a0.y + k2.y;
            sc[j][2] += a1.x + k2.x; sc[j][3] += a1.y + k2.y;
        }

        // ---- online softmax ----
        float tm0 = -1e30f, tm1 = -1e30f;
        #pragma unroll
        for (int j = 0; j < 8; j++) {
            tm0 = fmaxf(tm0, fmaxf(sc[j][0], sc[j][1]));
            tm1 = fmaxf(tm1, fmaxf(sc[j][2], sc[j][3]));
        }
        tm0 = fmaxf(tm0, __shfl_xor_sync(0xffffffffu, tm0, 1, 4));
        tm0 = fmaxf(tm0, __shfl_xor_sync(0xffffffffu, tm0, 2, 4));
        tm1 = fmaxf(tm1, __shfl_xor_sync(0xffffffffu, tm1, 1, 4));
        tm1 = fmaxf(tm1, __shfl_xor_sync(0xffffffffu, tm1, 2, 4));
        const float mn0 = fmaxf(m0, tm0), mn1 = fmaxf(m1, tm1);
        const float cr0 = __expf(m0 - mn0), cr1 = __expf(m1 - mn1);
        m0 = mn0; m1 = mn1;
        float rs0 = 0.f, rs1 = 0.f;
        #pragma unroll
        for (int j = 0; j < 8; j++) {
            sc[j][0] = __expf(sc[j][0] - mn0);
            sc[j][1] = __expf(sc[j][1] - mn0);
            sc[j][2] = __expf(sc[j][2] - mn1);
            sc[j][3] = __expf(sc[j][3] - mn1);
            rs0 += sc[j][0] + sc[j][1];
            rs1 += sc[j][2] + sc[j][3];
        }
        rs0 += __shfl_xor_sync(0xffffffffu, rs0, 1, 4);
        rs0 += __shfl_xor_sync(0xffffffffu, rs0, 2, 4);
        rs1 += __shfl_xor_sync(0xffffffffu, rs1, 1, 4);
        rs1 += __shfl_xor_sync(0xffffffffu, rs1, 2, 4);
        l0 = l0 * cr0 + rs0;
        l1 = l1 * cr1 + rs1;
        #pragma unroll
        for (int j = 0; j < 8; j++) {
            acc[j][0] *= cr0; acc[j][1] *= cr0;
            acc[j][2] *= cr1; acc[j][3] *= cr1;
        }

        // ---- PV: O += Ph Vh + Ph Vl + Pl Vh, term-major over ng pairs ----
        #pragma unroll
        for (int kk = 0; kk < 4; kk++) {
            const int j0 = 2 * kk, j1 = j0 + 1;
            uint32_t ph[4], pl[4];
            {
                float px[8] = {sc[j0][0], sc[j0][1], sc[j0][2], sc[j0][3],
                               sc[j1][0], sc[j1][1], sc[j1][2], sc[j1][3]};
                #pragma unroll
                for (int q = 0; q < 4; q++) {
                    uint32_t hp_ = packbf(px[2 * q], px[2 * q + 1]);
                    float2 hf = unpackbf(hp_);
                    ph[q] = hp_;
                    pl[q] = packbf(px[2 * q] - hf.x, px[2 * q + 1] - hf.y);
                }
            }
            #pragma unroll
            for (int ngp = 0; ngp < 2; ngp++) {
                uint32_t v4[2][4], w4[2][4];
                #pragma unroll
                for (int p = 0; p < 2; p++) {
                    const int ng = ngp * 2 + p;
                    const uint32_t a = fa_off(kk * 16 + lrow, ng * 2 + lseg);
                    ldsm4t(v4[p], stk + 16384 + a);
                    ldsm4t(w4[p], stk + 24576 + a);
                }
                #pragma unroll
                for (int term = 0; term < 3; term++) {
                    #pragma unroll
                    for (int p = 0; p < 2; p++) {
                        const int ng = ngp * 2 + p;
                        if (term == 0) {
                            mma_bf16(acc[ng * 2 + 0], ph, v4[p][0], v4[p][1]);
                            mma_bf16(acc[ng * 2 + 1], ph, v4[p][2], v4[p][3]);
                        } else if (term == 1) {
                            mma_bf16(acc[ng * 2 + 0], ph, w4[p][0], w4[p][1]);
                            mma_bf16(acc[ng * 2 + 1], ph, w4[p][2], w4[p][3]);
                        } else {
                            mma_bf16(acc[ng * 2 + 0], pl, v4[p][0], v4[p][1]);
                            mma_bf16(acc[ng * 2 + 1], pl, v4[p][2], v4[p][3]);
                        }
                    }
                }
            }
        }
    }

    // ---- epilogue: normalize, write ctx bf16 hi/lo [t*B+b][E] ----
    const float inv0 = 1.f / l0, inv1 = 1.f / l1;
    const int r0 = t0 + wm + qr, r1 = r0 + 8;
    #pragma unroll
    for (int j = 0; j < 8; j++) {
        const int col = h * D_ + j * 8 + qc;
        {
            float x = acc[j][0] * inv0, y = acc[j][1] * inv0;
            uint32_t hp_ = packbf(x, y);
            float2 hf = unpackbf(hp_);
            uint32_t lp_ = packbf(x - hf.x, y - hf.y);
            const size_t idx = ((size_t)r0 * B_ + b) * E_ + col;
            *(uint32_t*)&ch[idx] = hp_;
            *(uint32_t*)&cl[idx] = lp_;
        }
        {
            float x = acc[j][2] * inv1, y = acc[j][3] * inv1;
            uint32_t hp_ = packbf(x, y);
            float2 hf = unpackbf(hp_);
            uint32_t lp_ = packbf(x - hf.x, y - hf.y);
            const size_t idx = ((size_t)r1 * B_ + b) * E_ + col;
            *(uint32_t*)&ch[idx] = hp_;
            *(uint32_t*)&cl[idx] = lp_;
        }
    }
}

// ---------------------------------------------------------------------------
// Launch
// ---------------------------------------------------------------------------
extern "C" void kernel_launch(void* const* d_in, const int* in_sizes, int n_in,
                              void* d_out, int out_size)
{
    const float* query = (const float*)d_in[0];
    const float* key   = (const float*)d_in[1];
    const float* value = (const float*)d_in[2];
    const float* amask = (const float*)d_in[3];
    const unsigned char* kpad = (const unsigned char*)d_in[4];
    const float* Wq = (const float*)d_in[5];
    const float* bq = (const float*)d_in[6];
    const float* Wk = (const float*)d_in[7];
    const float* bk = (const float*)d_in[8];
    const float* Wv = (const float*)d_in[9];
    const float* bv = (const float*)d_in[10];
    const float* Wo = (const float*)d_in[11];
    const float* bo = (const float*)d_in[12];
    float* out = (float*)d_out;

    __nv_bfloat16 *iqh, *iql, *ikh, *ikl, *ivh, *ivl, *wh, *wl;
    __nv_bfloat16 *pqh, *pql, *pkh, *pkl, *pvh, *pvl, *ch, *cl;
    float* kpf;
    cudaGetSymbolAddress((void**)&iqh, g_iqh); cudaGetSymbolAddress((void**)&iql, g_iql);
    cudaGetSymbolAddress((void**)&ikh, g_ikh); cudaGetSymbolAddress((void**)&ikl, g_ikl);
    cudaGetSymbolAddress((void**)&ivh, g_ivh); cudaGetSymbolAddress((void**)&ivl, g_ivl);
    cudaGetSymbolAddress((void**)&wh, g_wh);   cudaGetSymbolAddress((void**)&wl, g_wl);
    cudaGetSymbolAddress((void**)&pqh, g_pqh); cudaGetSymbolAddress((void**)&pql, g_pql);
    cudaGetSymbolAddress((void**)&pkh, g_pkh); cudaGetSymbolAddress((void**)&pkl, g_pkl);
    cudaGetSymbolAddress((void**)&pvh, g_pvh); cudaGetSymbolAddress((void**)&pvl, g_pvl);
    cudaGetSymbolAddress((void**)&ch, g_ch);   cudaGetSymbolAddress((void**)&cl, g_cl);
    cudaGetSymbolAddress((void**)&kpf, g_kpf);

    cudaFuncSetAttribute(gemm_tc<0>, cudaFuncAttributeMaxDynamicSharedMemorySize, G_SMEM);
    cudaFuncSetAttribute(gemm_tc<1>, cudaFuncAttributeMaxDynamicSharedMemorySize, G_SMEM);
    cudaFuncSetAttribute(flash_mma, cudaFuncAttributeMaxDynamicSharedMemorySize, FA_SMEM);

    const int nIn4 = M_ * E_ / 4;
    const int nW4  = E_ * E_ / 4;

    CvtJobs cj;
    cj.j[0] = {(const float4*)query, (uint2*)iqh, (uint2*)iql, nIn4};
    cj.j[1] = {(const float4*)key,   (uint2*)ikh, (uint2*)ikl, nIn4};
    cj.j[2] = {(const float4*)value, (uint2*)ivh, (uint2*)ivl, nIn4};
    cj.j[3] = {(const float4*)Wq, (uint2*)(wh + 0 * E_ * E_), (uint2*)(wl + 0 * E_ * E_), nW4};
    cj.j[4] = {(const float4*)Wk, (uint2*)(wh + 1 * E_ * E_), (uint2*)(wl + 1 * E_ * E_), nW4};
    cj.j[5] = {(const float4*)Wv, (uint2*)(wh + 2 * E_ * E_), (uint2*)(wl + 2 * E_ * E_), nW4};
    cj.j[6] = {(const float4*)Wo, (uint2*)(wh + 3 * E_ * E_), (uint2*)(wl + 3 * E_ * E_), nW4};
    convert_all<<<dim3(nIn4 / 256, 7), 256>>>(cj);
    kpad_to_float<<<(B_ * S_ + 255) / 256, 256>>>(kpad, kpf, B_ * S_);

    // fused QKV projections (grid.z = 3)
    GemmJobs3 gq;
    gq.j[0] = {iqh, iql, wh + 0 * E_ * E_, wl + 0 * E_ * E_, bq, pqh, pql, nullptr, 0.125f};
    gq.j[1] = {ikh, ikl, wh + 1 * E_ * E_, wl + 1 * E_ * E_, bk, pkh, pkl, nullptr, 1.0f};
    gq.j[2] = {ivh, ivl, wh + 2 * E_ * E_, wl + 2 * E_ * E_, bv, pvh, pvl, nullptr, 1.0f};
    gemm_tc<0><<<dim3(M_ / 128, E_ / 128, 3), 256, G_SMEM>>>(gq);

    // flash attention: 64-row CTAs, 128 threads, 2 CTAs/SM
    dim3 fgrid(T_ / 64, H_, B_);
    flash_mma<<<fgrid, 128, FA_SMEM>>>(pqh, pql, pkh, pkl, pvh, pvl, amask, kpf, ch, cl);

    // output projection (fp32 out)
    GemmJobs3 go;
    go.j[0] = {ch, cl, wh + 3 * E_ * E_, wl + 3 * E_ * E_, bo, nullptr, nullptr, out, 1.0f};
    go.j[1] = go.j[0];
    go.j[2] = go.j[0];
    gemm_tc<1><<<dim3(M_ / 128, E_ / 128, 1), 256, G_SMEM>>>(go);
}